// round 8
// baseline (speedup 1.0000x reference)
#include <cuda_runtime.h>
#include <cstdint>

#define NMAX 50000
#define EMAX 800000
#define GNUM 512
#define HID 64
#define LAY 5
#define HL 320
#define BN_EPS 1e-5f
#define PB 592

// ---------------- static scratch ----------------
__device__ float g_z   [(size_t)NMAX * HID];
__device__ float g_outs[(size_t)NMAX * HL];
__device__ float g_stats[LAY * 256];
__device__ int   g_deg[NMAX];
__device__ int   g_rowptr[NMAX + 1];
__device__ int   g_cur[NMAX];
__device__ int   g_part[256];
__device__ int   g_partscan[256];
__device__ int   g_csrc[EMAX];
__device__ int   g_is64_e, g_is64_b;
__device__ int   g_tick[16];
__device__ unsigned g_count = 0, g_epoch = 0;

__device__ __forceinline__ long ldidx(const void* p, long i, int is64) {
    return is64 ? (long)((const long long*)p)[i] : (long)((const int*)p)[i];
}

__device__ __forceinline__ unsigned ld_epoch() {
    unsigned v;
    asm volatile("ld.global.cg.u32 %0, [%1];" : "=r"(v) : "l"(&g_epoch) : "memory");
    return v;
}

__device__ __forceinline__ void gbar() {
    __syncthreads();
    if (threadIdx.x == 0) {
        __threadfence();
        unsigned e = ld_epoch();
        if (atomicAdd(&g_count, 1) == gridDim.x - 1) {
            atomicExch(&g_count, 0u);
            __threadfence();
            atomicExch(&g_epoch, e + 1);
        } else {
            unsigned cur;
            do { __nanosleep(20); cur = ld_epoch(); } while (cur == e);
        }
        __threadfence();
    }
    __syncthreads();
}

// ---------------- shared memory ----------------
struct SmGemm {
    float w[64][64];
    float in[64][65];
    float a[64];
    float b[64];
    float bias[64];
};
struct SmPool { float a[HL]; float b[HL]; };
struct SmScan { int sh[257]; };
struct SmL0   { float xr[64]; };
union __align__(16) SmU {
    SmGemm g; SmPool p; SmScan s; SmL0 l0;
};

__global__ void __launch_bounds__(256, 4) fused_all(
    const float* __restrict__ x, const void* __restrict__ ei,
    const void* __restrict__ batch,
    const float* __restrict__ w1_0, const float* __restrict__ w1_rest,
    const float* __restrict__ b1,
    const float* __restrict__ gm, const float* __restrict__ bm,
    const float* __restrict__ w2, const float* __restrict__ b2,
    const float* __restrict__ go, const float* __restrict__ bo,
    const float* __restrict__ lin_w, const float* __restrict__ lin_b,
    float* __restrict__ out, int n, int E, int bcount, float invN)
{
    __shared__ SmU sm;
    __shared__ int s_tile;
    int t = threadIdx.x, b = blockIdx.x, nb = gridDim.x;
    int lane = t & 31, warp = t >> 5;
    long gstride = (long)nb * 256;

    // ---------- P0: zero + detect ----------
    for (long i = (long)b * 256 + t; i < n; i += gstride) g_deg[i] = 0;
    if (b == 0) {
        for (int i = t; i < LAY * 256; i += 256) g_stats[i] = 0.f;
        if (t < 16) g_tick[t] = 0;
    }
    if (b == 1) {
        const int* p = (const int*)ei;
        int f = 0;
        for (int i = t; i < 4096; i += 256) if (p[2 * i + 1] != 0) f = 1;
        f = __syncthreads_or(f);
        if (t == 0) g_is64_e = (f == 0);
        const int* q = (const int*)batch;
        int hf = bcount / 2;
        int f2 = 0;
        for (int i = t; i < 2048; i += 256) {
            int pos = hf - 1 - i;
            if (pos >= 0 && q[2 * pos + 1] != 0) f2 = 1;
        }
        f2 = __syncthreads_or(f2);
        if (t == 0) g_is64_b = (f2 == 0);
    }
    gbar();

    // ---------- P1: degree histogram ----------
    {
        int is64 = g_is64_e;
        for (long e0 = (long)b * 256 + t; e0 < E; e0 += gstride) {
            int dst = (int)ldidx(ei, (long)E + e0, is64);
            atomicAdd(&g_deg[dst], 1);
        }
    }
    gbar();

    int nch = (n + 255) / 256;

    // ---------- P2: chunk sums ----------
    for (int c = b; c < nch; c += nb) {
        int i = c * 256 + t;
        sm.s.sh[t] = (i < n) ? __ldcg(&g_deg[i]) : 0;
        __syncthreads();
        for (int off = 128; off > 0; off >>= 1) {
            if (t < off) sm.s.sh[t] += sm.s.sh[t + off];
            __syncthreads();
        }
        if (t == 0) g_part[c] = sm.s.sh[0];
        __syncthreads();
    }
    gbar();

    // ---------- P3: scan of chunk sums ----------
    if (b == 0) {
        int v = (t < nch) ? __ldcg(&g_part[t]) : 0;
        sm.s.sh[t] = v;
        __syncthreads();
        for (int off = 1; off < 256; off <<= 1) {
            int xv = (t >= off) ? sm.s.sh[t - off] : 0;
            __syncthreads();
            sm.s.sh[t] += xv;
            __syncthreads();
        }
        if (t < nch) g_partscan[t] = sm.s.sh[t] - v;
    }
    gbar();

    // ---------- P4: rowptr ----------
    for (int c = b; c < nch; c += nb) {
        int i = c * 256 + t;
        int v = (i < n) ? __ldcg(&g_deg[i]) : 0;
        sm.s.sh[t] = v;
        __syncthreads();
        for (int off = 1; off < 256; off <<= 1) {
            int xv = (t >= off) ? sm.s.sh[t - off] : 0;
            __syncthreads();
            sm.s.sh[t] += xv;
            __syncthreads();
        }
        if (i < n) {
            int rp = __ldcg(&g_partscan[c]) + sm.s.sh[t] - v;
            g_rowptr[i] = rp;
            g_cur[i] = rp;
            if (i == n - 1) g_rowptr[n] = E;
        }
        __syncthreads();
    }
    gbar();

    // ---------- P5: fill CSR ----------
    {
        int is64 = g_is64_e;
        for (long e0 = (long)b * 256 + t; e0 < E; e0 += gstride) {
            int src = (int)ldidx(ei, e0, is64);
            int dst = (int)ldidx(ei, (long)E + e0, is64);
            int pos = atomicAdd(&g_cur[dst], 1);
            g_csrc[pos] = src;
        }
    }
    gbar();

    int ntiles = (n + 63) / 64;

    // ---------- P6: layer-0 (stolen tiles) ----------
    for (;;) {
        __syncthreads();
        if (t == 0) s_tile = atomicAdd(&g_tick[0], 1);
        __syncthreads();
        int tile = s_tile;
        if (tile >= ntiles) break;
        int r0 = tile * 64;
        for (int rr = 0; rr < 8; rr++) {
            int rl = warp * 8 + rr;
            int row = r0 + rl;
            float acc = 0.f;
            if (row < n) {
                int beg = __ldcg(&g_rowptr[row]), end = __ldcg(&g_rowptr[row + 1]);
                for (int j = beg + lane; j < end; j += 32)
                    acc += x[__ldcg(&g_csrc[j])];
            }
            #pragma unroll
            for (int o = 16; o > 0; o >>= 1)
                acc += __shfl_xor_sync(0xFFFFFFFFu, acc, o);
            if (lane == 0)
                sm.l0.xr[rl] = (row < n) ? (acc + x[row]) : 0.f;
        }
        __syncthreads();
        int c = t & 63, g4 = t >> 6;
        float wc = w1_0[c], bc = b1[c];
        float s = 0.f, q = 0.f;
        #pragma unroll
        for (int i = 0; i < 16; i++) {
            int row = r0 + g4 * 16 + i;
            if (row < n) {
                float zv = sm.l0.xr[g4 * 16 + i] * wc + bc;
                g_z[(size_t)row * HID + c] = zv;
                s += zv; q += zv * zv;
            }
        }
        atomicAdd(&g_stats[c], s);
        atomicAdd(&g_stats[64 + c], q);
    }
    gbar();

    // ---------- layers ----------
    for (int l = 0; l < LAY; l++) {
        // ----- gemm1 + fused 4-edge gather (l >= 1) -----
        if (l > 0) {
            int pc = (l - 1) * HID;
            int pso = (l - 1) * 256 + 128;
            if (t < 64) {
                float mean = __ldcg(&g_stats[pso + t]) * invN;
                float var  = __ldcg(&g_stats[pso + 64 + t]) * invN - mean * mean;
                float a = go[pc + t] * rsqrtf(var + BN_EPS);
                sm.g.a[t] = a;
                sm.g.b[t] = bo[pc + t] - mean * a;
                sm.g.bias[t] = b1[l * HID + t];
            }
            const float* w = w1_rest + (size_t)(l - 1) * 4096;
            for (int idx = t; idx < 4096; idx += 256)
                sm.g.w[idx >> 6][idx & 63] = w[idx];
            __syncthreads();

            int qtr = lane >> 3;      // edge slot 0..3
            int i8  = lane & 7;       // covers floats i8*8 .. i8*8+7
            float4 ca0 = *(const float4*)&sm.g.a[i8 * 8];
            float4 ca1 = *(const float4*)&sm.g.a[i8 * 8 + 4];
            float4 cb0 = *(const float4*)&sm.g.b[i8 * 8];
            float4 cb1 = *(const float4*)&sm.g.b[i8 * 8 + 4];
            int so = l * 256;
            int tickid = 2 * l - 1;

            for (;;) {
                __syncthreads();
                if (t == 0) s_tile = atomicAdd(&g_tick[tickid], 1);
                __syncthreads();
                int tile = s_tile;
                if (tile >= ntiles) break;
                int r0 = tile * 64;

                for (int rr = 0; rr < 8; rr++) {
                    int rl = warp * 8 + rr;
                    int row = r0 + rl;
                    float4 A0 = make_float4(0.f,0.f,0.f,0.f);
                    float4 A1 = make_float4(0.f,0.f,0.f,0.f);
                    if (row < n) {
                        int beg = __ldcg(&g_rowptr[row]);
                        int end = __ldcg(&g_rowptr[row + 1]);
                        int jj = beg + qtr;
                        bool v = jj < end;
                        int srcn = v ? __ldcg(&g_csrc[jj]) : 0;
                        while (v) {
                            int src = srcn;
                            int j2 = jj + 4;
                            bool v2 = j2 < end;
                            srcn = v2 ? __ldcg(&g_csrc[j2]) : 0;
                            const float* rp = g_outs + (size_t)src * HL + pc + i8 * 8;
                            float4 x0 = __ldcg((const float4*)rp);
                            float4 x1 = __ldcg((const float4*)(rp + 4));
                            A0.x += fmaxf(fmaf(x0.x, ca0.x, cb0.x), 0.f);
                            A0.y += fmaxf(fmaf(x0.y, ca0.y, cb0.y), 0.f);
                            A0.z += fmaxf(fmaf(x0.z, ca0.z, cb0.z), 0.f);
                            A0.w += fmaxf(fmaf(x0.w, ca0.w, cb0.w), 0.f);
                            A1.x += fmaxf(fmaf(x1.x, ca1.x, cb1.x), 0.f);
                            A1.y += fmaxf(fmaf(x1.y, ca1.y, cb1.y), 0.f);
                            A1.z += fmaxf(fmaf(x1.z, ca1.z, cb1.z), 0.f);
                            A1.w += fmaxf(fmaf(x1.w, ca1.w, cb1.w), 0.f);
                            jj = j2; v = v2;
                        }
                    }
                    // combine the 4 quarters (same row, same channels)
                    #pragma unroll
                    for (int o = 8; o <= 16; o <<= 1) {
                        A0.x += __shfl_xor_sync(0xFFFFFFFFu, A0.x, o);
                        A0.y += __shfl_xor_sync(0xFFFFFFFFu, A0.y, o);
                        A0.z += __shfl_xor_sync(0xFFFFFFFFu, A0.z, o);
                        A0.w += __shfl_xor_sync(0xFFFFFFFFu, A0.w, o);
                        A1.x += __shfl_xor_sync(0xFFFFFFFFu, A1.x, o);
                        A1.y += __shfl_xor_sync(0xFFFFFFFFu, A1.y, o);
                        A1.z += __shfl_xor_sync(0xFFFFFFFFu, A1.z, o);
                        A1.w += __shfl_xor_sync(0xFFFFFFFFu, A1.w, o);
                    }
                    if (qtr == 0) {
                        if (row < n) {
                            const float* rp = g_outs + (size_t)row * HL + pc + i8 * 8;
                            float4 h0 = __ldcg((const float4*)rp);
                            float4 h1 = __ldcg((const float4*)(rp + 4));
                            A0.x += fmaxf(fmaf(h0.x, ca0.x, cb0.x), 0.f);
                            A0.y += fmaxf(fmaf(h0.y, ca0.y, cb0.y), 0.f);
                            A0.z += fmaxf(fmaf(h0.z, ca0.z, cb0.z), 0.f);
                            A0.w += fmaxf(fmaf(h0.w, ca0.w, cb0.w), 0.f);
                            A1.x += fmaxf(fmaf(h1.x, ca1.x, cb1.x), 0.f);
                            A1.y += fmaxf(fmaf(h1.y, ca1.y, cb1.y), 0.f);
                            A1.z += fmaxf(fmaf(h1.z, ca1.z, cb1.z), 0.f);
                            A1.w += fmaxf(fmaf(h1.w, ca1.w, cb1.w), 0.f);
                        }
                        float* ip = &sm.g.in[rl][i8 * 8];
                        ip[0] = A0.x; ip[1] = A0.y; ip[2] = A0.z; ip[3] = A0.w;
                        ip[4] = A1.x; ip[5] = A1.y; ip[6] = A1.z; ip[7] = A1.w;
                    }
                }
                __syncthreads();
                int r = t & 63, c0 = (t >> 6) * 16;
                float acc[16];
                #pragma unroll
                for (int j = 0; j < 16; j++) acc[j] = sm.g.bias[c0 + j];
                #pragma unroll
                for (int k = 0; k < 64; k++) {
                    float a = sm.g.in[r][k];
                    const float4* wrow = (const float4*)&sm.g.w[k][c0];
                    #pragma unroll
                    for (int m = 0; m < 4; m++) {
                        float4 wv = wrow[m];
                        acc[4*m+0] = fmaf(a, wv.x, acc[4*m+0]);
                        acc[4*m+1] = fmaf(a, wv.y, acc[4*m+1]);
                        acc[4*m+2] = fmaf(a, wv.z, acc[4*m+2]);
                        acc[4*m+3] = fmaf(a, wv.w, acc[4*m+3]);
                    }
                }
                int gr = r0 + r;
                bool valid = gr < n;
                if (valid) {
                    float4* op = (float4*)&g_z[(size_t)gr * HID + c0];
                    #pragma unroll
                    for (int m = 0; m < 4; m++)
                        op[m] = make_float4(acc[4*m], acc[4*m+1], acc[4*m+2], acc[4*m+3]);
                }
                #pragma unroll
                for (int j = 0; j < 16; j++) {
                    float s = valid ? acc[j] : 0.f;
                    float q = s * s;
                    #pragma unroll
                    for (int o = 16; o > 0; o >>= 1) {
                        s += __shfl_down_sync(0xFFFFFFFFu, s, o);
                        q += __shfl_down_sync(0xFFFFFFFFu, q, o);
                    }
                    if (lane == 0) {
                        atomicAdd(&g_stats[so + c0 + j], s);
                        atomicAdd(&g_stats[so + 64 + c0 + j], q);
                    }
                }
            }
            gbar();
        }

        // ----- gemm2 -----
        {
            int zso = l * 256;
            if (t < 64) {
                float mean = __ldcg(&g_stats[zso + t]) * invN;
                float var  = __ldcg(&g_stats[zso + 64 + t]) * invN - mean * mean;
                float a = gm[l * HID + t] * rsqrtf(var + BN_EPS);
                sm.g.a[t] = a;
                sm.g.b[t] = bm[l * HID + t] - mean * a;
                sm.g.bias[t] = b2[l * HID + t];
            }
            const float* w = w2 + (size_t)l * 4096;
            for (int idx = t; idx < 4096; idx += 256)
                sm.g.w[idx >> 6][idx & 63] = w[idx];
            __syncthreads();

            int vso = l * 256 + 128;
            int tickid = 8 + l;

            for (;;) {
                __syncthreads();
                if (t == 0) s_tile = atomicAdd(&g_tick[tickid], 1);
                __syncthreads();
                int tile = s_tile;
                if (tile >= ntiles) break;
                int r0 = tile * 64;
                for (int idx = t; idx < 1024; idx += 256) {
                    int r = idx >> 4, k4 = idx & 15;
                    int gr = r0 + r;
                    float4 val = make_float4(0.f, 0.f, 0.f, 0.f);
                    if (gr < n) {
                        float4 z = __ldcg((const float4*)(g_z + (size_t)gr * HID + k4 * 4));
                        val.x = fmaxf(fmaf(z.x, sm.g.a[k4*4+0], sm.g.b[k4*4+0]), 0.f);
                        val.y = fmaxf(fmaf(z.y, sm.g.a[k4*4+1], sm.g.b[k4*4+1]), 0.f);
                        val.z = fmaxf(fmaf(z.z, sm.g.a[k4*4+2], sm.g.b[k4*4+2]), 0.f);
                        val.w = fmaxf(fmaf(z.w, sm.g.a[k4*4+3], sm.g.b[k4*4+3]), 0.f);
                    }
                    sm.g.in[r][k4*4+0] = val.x;
                    sm.g.in[r][k4*4+1] = val.y;
                    sm.g.in[r][k4*4+2] = val.z;
                    sm.g.in[r][k4*4+3] = val.w;
                }
                __syncthreads();
                int r = t & 63, c0 = (t >> 6) * 16;
                float acc[16];
                #pragma unroll
                for (int j = 0; j < 16; j++) acc[j] = sm.g.bias[c0 + j];
                #pragma unroll
                for (int k = 0; k < 64; k++) {
                    float a = sm.g.in[r][k];
                    const float4* wrow = (const float4*)&sm.g.w[k][c0];
                    #pragma unroll
                    for (int m = 0; m < 4; m++) {
                        float4 wv = wrow[m];
                        acc[4*m+0] = fmaf(a, wv.x, acc[4*m+0]);
                        acc[4*m+1] = fmaf(a, wv.y, acc[4*m+1]);
                        acc[4*m+2] = fmaf(a, wv.z, acc[4*m+2]);
                        acc[4*m+3] = fmaf(a, wv.w, acc[4*m+3]);
                    }
                }
                int gr = r0 + r;
                bool valid = gr < n;
                if (valid) {
                    float4* op = (float4*)(g_outs + (size_t)gr * HL + l * HID + c0);
                    #pragma unroll
                    for (int m = 0; m < 4; m++)
                        op[m] = make_float4(acc[4*m], acc[4*m+1], acc[4*m+2], acc[4*m+3]);
                }
                #pragma unroll
                for (int j = 0; j < 16; j++) {
                    float s = valid ? acc[j] : 0.f;
                    float q = s * s;
                    #pragma unroll
                    for (int o = 16; o > 0; o >>= 1) {
                        s += __shfl_down_sync(0xFFFFFFFFu, s, o);
                        q += __shfl_down_sync(0xFFFFFFFFu, q, o);
                    }
                    if (lane == 0) {
                        atomicAdd(&g_stats[vso + c0 + j], s);
                        atomicAdd(&g_stats[vso + 64 + c0 + j], q);
                    }
                }
            }
            gbar();
        }
    }

    // ---------- pool + classifier (warp per graph, coalesced) ----------
    for (int c = t; c < HL; c += 256) {
        int l = c >> 6, ch = c & 63;
        int vso = l * 256 + 128;
        float mean = __ldcg(&g_stats[vso + ch]) * invN;
        float var  = __ldcg(&g_stats[vso + 64 + ch]) * invN - mean * mean;
        float a = go[c] * rsqrtf(var + BN_EPS);
        sm.p.a[c] = a;
        sm.p.b[c] = bo[c] - mean * a;
    }
    __syncthreads();
    {
        int is64 = g_is64_b;
        for (;;) {
            int g;
            if (lane == 0) g = atomicAdd(&g_tick[13], 1);
            g = __shfl_sync(0xFFFFFFFFu, g, 0);
            if (g >= GNUM) break;
            int se = n;
            if (lane < 2) {
                int key = g + lane;
                int lo = 0, hi = n;
                while (lo < hi) {
                    int mid = (lo + hi) >> 1;
                    if ((int)ldidx(batch, mid, is64) < key) lo = mid + 1;
                    else hi = mid;
                }
                se = lo;
            }
            int s0 = __shfl_sync(0xFFFFFFFFu, se, 0);
            int e0 = __shfl_sync(0xFFFFFFFFu, se, 1);
            float acc[10];
            #pragma unroll
            for (int k = 0; k < 10; k++) acc[k] = 0.f;
            float xsum = 0.f;
            for (int r = s0; r < e0; r++) {
                xsum += x[r];
                const float* rowp = g_outs + (size_t)r * HL;
                #pragma unroll
                for (int k = 0; k < 10; k++) {
                    float vv = __ldcg(rowp + k * 32 + lane);
                    int c = k * 32 + lane;
                    acc[k] += fmaxf(fmaf(vv, sm.p.a[c], sm.p.b[c]), 0.f);
                }
            }
            float o0 = 0.f, o1 = 0.f;
            #pragma unroll
            for (int k = 0; k < 10; k++) {
                int c = k * 32 + lane;
                o0 = fmaf(acc[k], lin_w[(1 + c) * 2 + 0], o0);
                o1 = fmaf(acc[k], lin_w[(1 + c) * 2 + 1], o1);
            }
            #pragma unroll
            for (int o = 16; o > 0; o >>= 1) {
                o0 += __shfl_down_sync(0xFFFFFFFFu, o0, o);
                o1 += __shfl_down_sync(0xFFFFFFFFu, o1, o);
            }
            if (lane == 0) {
                out[g * 2 + 0] = o0 + xsum * lin_w[0] + lin_b[0];
                out[g * 2 + 1] = o1 + xsum * lin_w[1] + lin_b[1];
            }
        }
    }
}

// ---------------- launch ----------------
extern "C" void kernel_launch(void* const* d_in, const int* in_sizes, int n_in,
                              void* d_out, int out_size)
{
    const float* x      = (const float*)d_in[0];
    const void*  ei     = d_in[1];
    const void*  batch  = d_in[2];
    const float* w1_0   = (const float*)d_in[3];
    const float* w1_rest= (const float*)d_in[4];
    const float* b1     = (const float*)d_in[5];
    const float* gm     = (const float*)d_in[6];
    const float* bm     = (const float*)d_in[7];
    const float* w2     = (const float*)d_in[8];
    const float* b2     = (const float*)d_in[9];
    const float* go     = (const float*)d_in[10];
    const float* bo     = (const float*)d_in[11];
    const float* lin_w  = (const float*)d_in[12];
    const float* lin_b  = (const float*)d_in[13];
    float* out = (float*)d_out;

    int N = in_sizes[0];
    int E = in_sizes[1] / 2;
    float invN = 1.f / (float)N;

    fused_all<<<PB, 256>>>(x, ei, batch, w1_0, w1_rest, b1, gm, bm,
                           w2, b2, go, bo, lin_w, lin_b, out,
                           N, E, in_sizes[2], invN);
}

// round 9
// speedup vs baseline: 1.1325x; 1.1325x over previous
#include <cuda_runtime.h>
#include <cuda_fp16.h>
#include <cstdint>

#define NMAX 50000
#define EMAX 800000
#define GNUM 512
#define HID 64
#define LAY 5
#define HL 320
#define BN_EPS 1e-5f
#define PB 592
#define NSLICE 16
#define STATSZ (LAY * 256)

// ---------------- static scratch ----------------
__device__ float  g_z[(size_t)NMAX * HID];
__device__ __half g_h16[(size_t)NMAX * HL];     // RAW gemm2 outputs (pre-BN), fp16
__device__ float  g_statp[NSLICE * STATSZ];     // sliced stats: [slice][layer*256 + ...]
__device__ int    g_deg[NMAX];
__device__ int    g_rowptr[NMAX + 1];
__device__ int    g_cur[NMAX];
__device__ int    g_part[256];
__device__ int    g_partscan[256];
__device__ int    g_csrc[EMAX];
__device__ int    g_is64_e, g_is64_b;
__device__ unsigned g_count = 0, g_epoch = 0;

__device__ __forceinline__ long ldidx(const void* p, long i, int is64) {
    return is64 ? (long)((const long long*)p)[i] : (long)((const int*)p)[i];
}

__device__ __forceinline__ unsigned ld_epoch() {
    unsigned v;
    asm volatile("ld.global.cg.u32 %0, [%1];" : "=r"(v) : "l"(&g_epoch) : "memory");
    return v;
}

__device__ __forceinline__ void gbar() {
    __syncthreads();
    if (threadIdx.x == 0) {
        __threadfence();
        unsigned e = ld_epoch();
        if (atomicAdd(&g_count, 1) == gridDim.x - 1) {
            atomicExch(&g_count, 0u);
            __threadfence();
            atomicExch(&g_epoch, e + 1);
        } else {
            unsigned cur;
            do { __nanosleep(20); cur = ld_epoch(); } while (cur == e);
        }
        __threadfence();
    }
    __syncthreads();
}

// ---------------- shared memory ----------------
struct SmGemm {
    float w[64][64];
    float in[64][65];
    float a[64];
    float b[64];
    float bias[64];
    float st[128];       // block-local stat accumulator (sum[64], sq[64])
};
struct SmPool { float a[HL]; float b[HL]; };
struct SmScan { int sh[257]; };
struct SmL0   { float xr[64]; float st[128]; };
union __align__(16) SmU {
    SmGemm g; SmPool p; SmScan s; SmL0 l0;
};

__global__ void __launch_bounds__(256, 4) fused_all(
    const float* __restrict__ x, const void* __restrict__ ei,
    const void* __restrict__ batch,
    const float* __restrict__ w1_0, const float* __restrict__ w1_rest,
    const float* __restrict__ b1,
    const float* __restrict__ gm, const float* __restrict__ bm,
    const float* __restrict__ w2, const float* __restrict__ b2,
    const float* __restrict__ go, const float* __restrict__ bo,
    const float* __restrict__ lin_w, const float* __restrict__ lin_b,
    float* __restrict__ out, int n, int E, int bcount, float invN)
{
    __shared__ SmU sm;
    int t = threadIdx.x, b = blockIdx.x, nb = gridDim.x;
    int lane = t & 31, warp = t >> 5;
    long gstride = (long)nb * 256;
    int slice = (b & (NSLICE - 1)) * STATSZ;

    // ---------- P0: zero deg + sliced stats + detect ----------
    for (long i = (long)b * 256 + t; i < n; i += gstride) g_deg[i] = 0;
    for (long i = (long)b * 256 + t; i < NSLICE * STATSZ; i += gstride) g_statp[i] = 0.f;
    if (b == 1) {
        const int* p = (const int*)ei;
        int f = 0;
        for (int i = t; i < 4096; i += 256) if (p[2 * i + 1] != 0) f = 1;
        f = __syncthreads_or(f);
        if (t == 0) g_is64_e = (f == 0);
        const int* q = (const int*)batch;
        int hf = bcount / 2;
        int f2 = 0;
        for (int i = t; i < 2048; i += 256) {
            int pos = hf - 1 - i;
            if (pos >= 0 && q[2 * pos + 1] != 0) f2 = 1;
        }
        f2 = __syncthreads_or(f2);
        if (t == 0) g_is64_b = (f2 == 0);
    }
    gbar();

    // ---------- P1: degree histogram ----------
    {
        int is64 = g_is64_e;
        for (long e0 = (long)b * 256 + t; e0 < E; e0 += gstride) {
            int dst = (int)ldidx(ei, (long)E + e0, is64);
            atomicAdd(&g_deg[dst], 1);
        }
    }
    gbar();

    int nch = (n + 255) / 256;

    // ---------- P2: chunk sums ----------
    for (int c = b; c < nch; c += nb) {
        int i = c * 256 + t;
        sm.s.sh[t] = (i < n) ? g_deg[i] : 0;
        __syncthreads();
        for (int off = 128; off > 0; off >>= 1) {
            if (t < off) sm.s.sh[t] += sm.s.sh[t + off];
            __syncthreads();
        }
        if (t == 0) g_part[c] = sm.s.sh[0];
        __syncthreads();
    }
    gbar();

    // ---------- P3: scan of chunk sums ----------
    if (b == 0) {
        int v = (t < nch) ? g_part[t] : 0;
        sm.s.sh[t] = v;
        __syncthreads();
        for (int off = 1; off < 256; off <<= 1) {
            int xv = (t >= off) ? sm.s.sh[t - off] : 0;
            __syncthreads();
            sm.s.sh[t] += xv;
            __syncthreads();
        }
        if (t < nch) g_partscan[t] = sm.s.sh[t] - v;
    }
    gbar();

    // ---------- P4: rowptr ----------
    for (int c = b; c < nch; c += nb) {
        int i = c * 256 + t;
        int v = (i < n) ? g_deg[i] : 0;
        sm.s.sh[t] = v;
        __syncthreads();
        for (int off = 1; off < 256; off <<= 1) {
            int xv = (t >= off) ? sm.s.sh[t - off] : 0;
            __syncthreads();
            sm.s.sh[t] += xv;
            __syncthreads();
        }
        if (i < n) {
            int rp = g_partscan[c] + sm.s.sh[t] - v;
            g_rowptr[i] = rp;
            g_cur[i] = rp;
            if (i == n - 1) g_rowptr[n] = E;
        }
        __syncthreads();
    }
    gbar();

    // ---------- P5: fill CSR ----------
    {
        int is64 = g_is64_e;
        for (long e0 = (long)b * 256 + t; e0 < E; e0 += gstride) {
            int src = (int)ldidx(ei, e0, is64);
            int dst = (int)ldidx(ei, (long)E + e0, is64);
            int pos = atomicAdd(&g_cur[dst], 1);
            g_csrc[pos] = src;
        }
    }
    gbar();

    int ntiles = (n + 63) / 64;

    // ---------- P6: layer-0 agg + outer-product + stats (smem accum) ----------
    for (int i = t; i < 128; i += 256) sm.l0.st[i] = 0.f;
    __syncthreads();
    for (int tile = b; tile < ntiles; tile += nb) {
        int r0 = tile * 64;
        for (int rr = 0; rr < 8; rr++) {
            int rl = warp * 8 + rr;
            int row = r0 + rl;
            float acc = 0.f;
            if (row < n) {
                int beg = g_rowptr[row], end = g_rowptr[row + 1];
                for (int j = beg + lane; j < end; j += 32)
                    acc += x[g_csrc[j]];
            }
            #pragma unroll
            for (int o = 16; o > 0; o >>= 1)
                acc += __shfl_xor_sync(0xFFFFFFFFu, acc, o);
            if (lane == 0)
                sm.l0.xr[rl] = (row < n) ? (acc + x[row]) : 0.f;
        }
        __syncthreads();
        int c = t & 63, g4 = t >> 6;
        float wc = w1_0[c], bc = b1[c];
        float s = 0.f, q = 0.f;
        #pragma unroll
        for (int i = 0; i < 16; i++) {
            int row = r0 + g4 * 16 + i;
            if (row < n) {
                float zv = sm.l0.xr[g4 * 16 + i] * wc + bc;
                g_z[(size_t)row * HID + c] = zv;
                s += zv; q += zv * zv;
            }
        }
        atomicAdd(&sm.l0.st[c], s);
        atomicAdd(&sm.l0.st[64 + c], q);
        __syncthreads();
    }
    if (t < 128) atomicAdd(&g_statp[slice + t], sm.l0.st[t]);
    gbar();

    // ---------- layers ----------
    for (int l = 0; l < LAY; l++) {
        // ----- gemm1 + fused fp16 gather (l >= 1) -----
        if (l > 0) {
            int pc = (l - 1) * HID;
            int pso = (l - 1) * 256 + 128;
            if (t < 64) {
                float s1 = 0.f, s2 = 0.f;
                #pragma unroll 4
                for (int sl = 0; sl < NSLICE; sl++) {
                    const float* sp = g_statp + sl * STATSZ + pso;
                    s1 += __ldcg(sp + t);
                    s2 += __ldcg(sp + 64 + t);
                }
                float mean = s1 * invN;
                float var  = s2 * invN - mean * mean;
                float a = go[pc + t] * rsqrtf(var + BN_EPS);
                sm.g.a[t] = a;
                sm.g.b[t] = bo[pc + t] - mean * a;
                sm.g.bias[t] = b1[l * HID + t];
            }
            const float* w = w1_rest + (size_t)(l - 1) * 4096;
            for (int idx = t; idx < 4096; idx += 256)
                sm.g.w[idx >> 6][idx & 63] = w[idx];
            for (int i = t; i < 128; i += 256) sm.g.st[i] = 0.f;
            __syncthreads();

            int half = lane >> 4, c4 = lane & 15;
            float4 ca = *(const float4*)&sm.g.a[c4 * 4];
            float4 cb = *(const float4*)&sm.g.b[c4 * 4];
            int so = l * 256;

            for (int tile = b; tile < ntiles; tile += nb) {
                int r0 = tile * 64;
                for (int rr = 0; rr < 8; rr++) {
                    int rl = warp * 8 + rr;
                    int row = r0 + rl;
                    float4 A = make_float4(0.f, 0.f, 0.f, 0.f);
                    if (row < n) {
                        int beg = g_rowptr[row], end = g_rowptr[row + 1];
                        for (int j = beg + half; j < end; j += 2) {
                            int src = g_csrc[j];
                            uint2 raw = *(const uint2*)(g_h16 + (size_t)src * HL + pc + c4 * 4);
                            float2 f01 = __half22float2(*(__half2*)&raw.x);
                            float2 f23 = __half22float2(*(__half2*)&raw.y);
                            A.x += fmaxf(fmaf(f01.x, ca.x, cb.x), 0.f);
                            A.y += fmaxf(fmaf(f01.y, ca.y, cb.y), 0.f);
                            A.z += fmaxf(fmaf(f23.x, ca.z, cb.z), 0.f);
                            A.w += fmaxf(fmaf(f23.y, ca.w, cb.w), 0.f);
                        }
                    }
                    A.x += __shfl_xor_sync(0xFFFFFFFFu, A.x, 16);
                    A.y += __shfl_xor_sync(0xFFFFFFFFu, A.y, 16);
                    A.z += __shfl_xor_sync(0xFFFFFFFFu, A.z, 16);
                    A.w += __shfl_xor_sync(0xFFFFFFFFu, A.w, 16);
                    if (half == 0) {
                        if (row < n) {
                            uint2 raw = *(const uint2*)(g_h16 + (size_t)row * HL + pc + c4 * 4);
                            float2 f01 = __half22float2(*(__half2*)&raw.x);
                            float2 f23 = __half22float2(*(__half2*)&raw.y);
                            A.x += fmaxf(fmaf(f01.x, ca.x, cb.x), 0.f);
                            A.y += fmaxf(fmaf(f01.y, ca.y, cb.y), 0.f);
                            A.z += fmaxf(fmaf(f23.x, ca.z, cb.z), 0.f);
                            A.w += fmaxf(fmaf(f23.y, ca.w, cb.w), 0.f);
                        }
                        float* ip = &sm.g.in[rl][c4 * 4];
                        ip[0] = A.x; ip[1] = A.y; ip[2] = A.z; ip[3] = A.w;
                    }
                }
                __syncthreads();
                int r = t & 63, c0 = (t >> 6) * 16;
                float acc[16];
                #pragma unroll
                for (int j = 0; j < 16; j++) acc[j] = sm.g.bias[c0 + j];
                #pragma unroll
                for (int k = 0; k < 64; k++) {
                    float a = sm.g.in[r][k];
                    const float4* wrow = (const float4*)&sm.g.w[k][c0];
                    #pragma unroll
                    for (int m = 0; m < 4; m++) {
                        float4 wv = wrow[m];
                        acc[4*m+0] = fmaf(a, wv.x, acc[4*m+0]);
                        acc[4*m+1] = fmaf(a, wv.y, acc[4*m+1]);
                        acc[4*m+2] = fmaf(a, wv.z, acc[4*m+2]);
                        acc[4*m+3] = fmaf(a, wv.w, acc[4*m+3]);
                    }
                }
                int gr = r0 + r;
                bool valid = gr < n;
                if (valid) {
                    float4* op = (float4*)&g_z[(size_t)gr * HID + c0];
                    #pragma unroll
                    for (int m = 0; m < 4; m++)
                        op[m] = make_float4(acc[4*m], acc[4*m+1], acc[4*m+2], acc[4*m+3]);
                }
                #pragma unroll
                for (int j = 0; j < 16; j++) {
                    float s = valid ? acc[j] : 0.f;
                    float q = s * s;
                    #pragma unroll
                    for (int o = 16; o > 0; o >>= 1) {
                        s += __shfl_down_sync(0xFFFFFFFFu, s, o);
                        q += __shfl_down_sync(0xFFFFFFFFu, q, o);
                    }
                    if (lane == 0) {
                        atomicAdd(&sm.g.st[c0 + j], s);
                        atomicAdd(&sm.g.st[64 + c0 + j], q);
                    }
                }
                __syncthreads();
            }
            if (t < 128) atomicAdd(&g_statp[slice + so + t], sm.g.st[t]);
            gbar();
        }

        // ----- gemm2: z -> raw fp16 h, stats (smem accum) -----
        {
            int zso = l * 256;
            if (t < 64) {
                float s1 = 0.f, s2 = 0.f;
                #pragma unroll 4
                for (int sl = 0; sl < NSLICE; sl++) {
                    const float* sp = g_statp + sl * STATSZ + zso;
                    s1 += __ldcg(sp + t);
                    s2 += __ldcg(sp + 64 + t);
                }
                float mean = s1 * invN;
                float var  = s2 * invN - mean * mean;
                float a = gm[l * HID + t] * rsqrtf(var + BN_EPS);
                sm.g.a[t] = a;
                sm.g.b[t] = bm[l * HID + t] - mean * a;
                sm.g.bias[t] = b2[l * HID + t];
            }
            const float* w = w2 + (size_t)l * 4096;
            for (int idx = t; idx < 4096; idx += 256)
                sm.g.w[idx >> 6][idx & 63] = w[idx];
            for (int i = t; i < 128; i += 256) sm.g.st[i] = 0.f;
            __syncthreads();

            int vso = l * 256 + 128;

            for (int tile = b; tile < ntiles; tile += nb) {
                int r0 = tile * 64;
                for (int idx = t; idx < 1024; idx += 256) {
                    int r = idx >> 4, k4 = idx & 15;
                    int gr = r0 + r;
                    float4 val = make_float4(0.f, 0.f, 0.f, 0.f);
                    if (gr < n) {
                        float4 z = *(const float4*)(g_z + (size_t)gr * HID + k4 * 4);
                        val.x = fmaxf(fmaf(z.x, sm.g.a[k4*4+0], sm.g.b[k4*4+0]), 0.f);
                        val.y = fmaxf(fmaf(z.y, sm.g.a[k4*4+1], sm.g.b[k4*4+1]), 0.f);
                        val.z = fmaxf(fmaf(z.z, sm.g.a[k4*4+2], sm.g.b[k4*4+2]), 0.f);
                        val.w = fmaxf(fmaf(z.w, sm.g.a[k4*4+3], sm.g.b[k4*4+3]), 0.f);
                    }
                    sm.g.in[r][k4*4+0] = val.x;
                    sm.g.in[r][k4*4+1] = val.y;
                    sm.g.in[r][k4*4+2] = val.z;
                    sm.g.in[r][k4*4+3] = val.w;
                }
                __syncthreads();
                int r = t & 63, c0 = (t >> 6) * 16;
                float acc[16];
                #pragma unroll
                for (int j = 0; j < 16; j++) acc[j] = sm.g.bias[c0 + j];
                #pragma unroll
                for (int k = 0; k < 64; k++) {
                    float a = sm.g.in[r][k];
                    const float4* wrow = (const float4*)&sm.g.w[k][c0];
                    #pragma unroll
                    for (int m = 0; m < 4; m++) {
                        float4 wv = wrow[m];
                        acc[4*m+0] = fmaf(a, wv.x, acc[4*m+0]);
                        acc[4*m+1] = fmaf(a, wv.y, acc[4*m+1]);
                        acc[4*m+2] = fmaf(a, wv.z, acc[4*m+2]);
                        acc[4*m+3] = fmaf(a, wv.w, acc[4*m+3]);
                    }
                }
                int gr = r0 + r;
                bool valid = gr < n;
                if (valid) {
                    uint4 pk[2];
                    __half2* ph = (__half2*)pk;
                    #pragma unroll
                    for (int m = 0; m < 8; m++)
                        ph[m] = __float22half2_rn(make_float2(acc[2*m], acc[2*m+1]));
                    uint4* op = (uint4*)(g_h16 + (size_t)gr * HL + l * HID + c0);
                    op[0] = pk[0];
                    op[1] = pk[1];
                }
                #pragma unroll
                for (int j = 0; j < 16; j++) {
                    float s = valid ? acc[j] : 0.f;
                    float q = s * s;
                    #pragma unroll
                    for (int o = 16; o > 0; o >>= 1) {
                        s += __shfl_down_sync(0xFFFFFFFFu, s, o);
                        q += __shfl_down_sync(0xFFFFFFFFu, q, o);
                    }
                    if (lane == 0) {
                        atomicAdd(&sm.g.st[c0 + j], s);
                        atomicAdd(&sm.g.st[64 + c0 + j], q);
                    }
                }
                __syncthreads();
            }
            if (t < 128) atomicAdd(&g_statp[slice + vso + t], sm.g.st[t]);
            gbar();
        }
    }

    // ---------- pool + classifier (warp per graph, fp16 reads) ----------
    for (int c = t; c < HL; c += 256) {
        int l = c >> 6, ch = c & 63;
        int vso = l * 256 + 128;
        float s1 = 0.f, s2 = 0.f;
        for (int sl = 0; sl < NSLICE; sl++) {
            const float* sp = g_statp + sl * STATSZ + vso;
            s1 += __ldcg(sp + ch);
            s2 += __ldcg(sp + 64 + ch);
        }
        float mean = s1 * invN;
        float var  = s2 * invN - mean * mean;
        float a = go[c] * rsqrtf(var + BN_EPS);
        sm.p.a[c] = a;
        sm.p.b[c] = bo[c] - mean * a;
    }
    __syncthreads();
    {
        int is64 = g_is64_b;
        int warpsTotal = nb * 8;
        int gw = b * 8 + warp;
        for (int g = gw; g < GNUM; g += warpsTotal) {
            int se = n;
            if (lane < 2) {
                int key = g + lane;
                int lo = 0, hi = n;
                while (lo < hi) {
                    int mid = (lo + hi) >> 1;
                    if ((int)ldidx(batch, mid, is64) < key) lo = mid + 1;
                    else hi = mid;
                }
                se = lo;
            }
            int s0 = __shfl_sync(0xFFFFFFFFu, se, 0);
            int e0 = __shfl_sync(0xFFFFFFFFu, se, 1);
            float acc[10];
            #pragma unroll
            for (int k = 0; k < 10; k++) acc[k] = 0.f;
            float xsum = 0.f;
            for (int r = s0; r < e0; r++) {
                xsum += x[r];
                const __half* rowp = g_h16 + (size_t)r * HL;
                #pragma unroll
                for (int k = 0; k < 10; k++) {
                    float vv = __half2float(rowp[k * 32 + lane]);
                    int c = k * 32 + lane;
                    acc[k] += fmaxf(fmaf(vv, sm.p.a[c], sm.p.b[c]), 0.f);
                }
            }
            float o0 = 0.f, o1 = 0.f;
            #pragma unroll
            for (int k = 0; k < 10; k++) {
                int c = k * 32 + lane;
                o0 = fmaf(acc[k], lin_w[(1 + c) * 2 + 0], o0);
                o1 = fmaf(acc[k], lin_w[(1 + c) * 2 + 1], o1);
            }
            #pragma unroll
            for (int o = 16; o > 0; o >>= 1) {
                o0 += __shfl_down_sync(0xFFFFFFFFu, o0, o);
                o1 += __shfl_down_sync(0xFFFFFFFFu, o1, o);
            }
            if (lane == 0) {
                out[g * 2 + 0] = o0 + xsum * lin_w[0] + lin_b[0];
                out[g * 2 + 1] = o1 + xsum * lin_w[1] + lin_b[1];
            }
        }
    }
}

// ---------------- launch ----------------
extern "C" void kernel_launch(void* const* d_in, const int* in_sizes, int n_in,
                              void* d_out, int out_size)
{
    const float* x      = (const float*)d_in[0];
    const void*  ei     = d_in[1];
    const void*  batch  = d_in[2];
    const float* w1_0   = (const float*)d_in[3];
    const float* w1_rest= (const float*)d_in[4];
    const float* b1     = (const float*)d_in[5];
    const float* gm     = (const float*)d_in[6];
    const float* bm     = (const float*)d_in[7];
    const float* w2     = (const float*)d_in[8];
    const float* b2     = (const float*)d_in[9];
    const float* go     = (const float*)d_in[10];
    const float* bo     = (const float*)d_in[11];
    const float* lin_w  = (const float*)d_in[12];
    const float* lin_b  = (const float*)d_in[13];
    float* out = (float*)d_out;

    int N = in_sizes[0];
    int E = in_sizes[1] / 2;
    float invN = 1.f / (float)N;

    fused_all<<<PB, 256>>>(x, ei, batch, w1_0, w1_rest, b1, gm, bm,
                           w2, b2, go, bo, lin_w, lin_b, out,
                           N, E, in_sizes[2], invN);
}

// round 10
// speedup vs baseline: 2.0921x; 1.8473x over previous
#include <cuda_runtime.h>
#include <cuda_fp16.h>
#include <cstdint>

#define NMAX 50000
#define EMAX 800000
#define GNUM 512
#define HID 64
#define LAY 5
#define HL 320
#define BN_EPS 1e-5f
#define PB 444
#define NT 512
#define NSLICE 16
#define STATSZ (LAY * 256)

// ---------------- static scratch ----------------
__device__ float  g_z[(size_t)NMAX * HID];
__device__ __half g_h16[(size_t)NMAX * HL];
__device__ float  g_statp[NSLICE * STATSZ];
__device__ int    g_deg[NMAX];
__device__ int    g_rowptr[NMAX + 1];
__device__ int    g_cur[NMAX];
__device__ int    g_part[256];
__device__ int    g_partscan[256];
__device__ int    g_csrc[EMAX];
__device__ int    g_is64_e, g_is64_b;
__device__ unsigned g_count = 0, g_epoch = 0;

__device__ __forceinline__ long ldidx(const void* p, long i, int is64) {
    return is64 ? (long)((const long long*)p)[i] : (long)((const int*)p)[i];
}

__device__ __forceinline__ unsigned ld_epoch() {
    unsigned v;
    asm volatile("ld.global.cg.u32 %0, [%1];" : "=r"(v) : "l"(&g_epoch) : "memory");
    return v;
}

__device__ __forceinline__ void gbar() {
    __syncthreads();
    if (threadIdx.x == 0) {
        __threadfence();
        unsigned e = ld_epoch();
        if (atomicAdd(&g_count, 1) == gridDim.x - 1) {
            atomicExch(&g_count, 0u);
            __threadfence();
            atomicExch(&g_epoch, e + 1);
        } else {
            unsigned cur;
            do { __nanosleep(20); cur = ld_epoch(); } while (cur == e);
        }
        __threadfence();
    }
    __syncthreads();
}

// ---------------- shared memory ----------------
struct SmGemm {
    float w[64][64];
    float in[64][65];
    float a[64];
    float b[64];
    float bias[64];
    float st[128];
};
struct SmPool { float a[HL]; float b[HL]; };
struct SmScan { int sh[NT + 1]; };
struct SmL0   { float xr[64]; float st[128]; };
union __align__(16) SmU {
    SmGemm g; SmPool p; SmScan s; SmL0 l0;
};

__global__ void __launch_bounds__(NT, 3) fused_all(
    const float* __restrict__ x, const void* __restrict__ ei,
    const void* __restrict__ batch,
    const float* __restrict__ w1_0, const float* __restrict__ w1_rest,
    const float* __restrict__ b1,
    const float* __restrict__ gm, const float* __restrict__ bm,
    const float* __restrict__ w2, const float* __restrict__ b2,
    const float* __restrict__ go, const float* __restrict__ bo,
    const float* __restrict__ lin_w, const float* __restrict__ lin_b,
    float* __restrict__ out, int n, int E, int bcount, float invN)
{
    __shared__ SmU sm;
    int t = threadIdx.x, b = blockIdx.x, nb = gridDim.x;
    int lane = t & 31, warp = t >> 5;
    long gstride = (long)nb * NT;
    int slice = (b & (NSLICE - 1)) * STATSZ;

    // ---------- P0: zero + detect ----------
    for (long i = (long)b * NT + t; i < n; i += gstride) g_deg[i] = 0;
    for (long i = (long)b * NT + t; i < NSLICE * STATSZ; i += gstride) g_statp[i] = 0.f;
    if (b == 1) {
        const int* p = (const int*)ei;
        int f = 0;
        for (int i = t; i < 4096; i += NT) if (p[2 * i + 1] != 0) f = 1;
        f = __syncthreads_or(f);
        if (t == 0) g_is64_e = (f == 0);
        const int* q = (const int*)batch;
        int hf = bcount / 2;
        int f2 = 0;
        for (int i = t; i < 2048; i += NT) {
            int pos = hf - 1 - i;
            if (pos >= 0 && q[2 * pos + 1] != 0) f2 = 1;
        }
        f2 = __syncthreads_or(f2);
        if (t == 0) g_is64_b = (f2 == 0);
    }
    gbar();

    // ---------- P1: degree histogram ----------
    {
        int is64 = g_is64_e;
        for (long e0 = (long)b * NT + t; e0 < E; e0 += gstride) {
            int dst = (int)ldidx(ei, (long)E + e0, is64);
            atomicAdd(&g_deg[dst], 1);
        }
    }
    gbar();

    int nch = (n + NT - 1) / NT;

    // ---------- P2: chunk sums ----------
    for (int c = b; c < nch; c += nb) {
        int i = c * NT + t;
        sm.s.sh[t] = (i < n) ? g_deg[i] : 0;
        __syncthreads();
        for (int off = NT / 2; off > 0; off >>= 1) {
            if (t < off) sm.s.sh[t] += sm.s.sh[t + off];
            __syncthreads();
        }
        if (t == 0) g_part[c] = sm.s.sh[0];
        __syncthreads();
    }
    gbar();

    // ---------- P3: scan of chunk sums ----------
    if (b == 0) {
        int v = (t < nch) ? g_part[t] : 0;
        sm.s.sh[t] = v;
        __syncthreads();
        for (int off = 1; off < NT; off <<= 1) {
            int xv = (t >= off) ? sm.s.sh[t - off] : 0;
            __syncthreads();
            sm.s.sh[t] += xv;
            __syncthreads();
        }
        if (t < nch) g_partscan[t] = sm.s.sh[t] - v;
    }
    gbar();

    // ---------- P4: rowptr ----------
    for (int c = b; c < nch; c += nb) {
        int i = c * NT + t;
        int v = (i < n) ? g_deg[i] : 0;
        sm.s.sh[t] = v;
        __syncthreads();
        for (int off = 1; off < NT; off <<= 1) {
            int xv = (t >= off) ? sm.s.sh[t - off] : 0;
            __syncthreads();
            sm.s.sh[t] += xv;
            __syncthreads();
        }
        if (i < n) {
            int rp = g_partscan[c] + sm.s.sh[t] - v;
            g_rowptr[i] = rp;
            g_cur[i] = rp;
            if (i == n - 1) g_rowptr[n] = E;
        }
        __syncthreads();
    }
    gbar();

    // ---------- P5: fill CSR ----------
    {
        int is64 = g_is64_e;
        for (long e0 = (long)b * NT + t; e0 < E; e0 += gstride) {
            int src = (int)ldidx(ei, e0, is64);
            int dst = (int)ldidx(ei, (long)E + e0, is64);
            int pos = atomicAdd(&g_cur[dst], 1);
            g_csrc[pos] = src;
        }
    }
    gbar();

    int ntiles = (n + 63) / 64;

    // ---------- P6: layer-0 (16 warps x 4 rows) ----------
    for (int i = t; i < 128; i += NT) sm.l0.st[i] = 0.f;
    __syncthreads();
    for (int tile = b; tile < ntiles; tile += nb) {
        int r0 = tile * 64;
        for (int rr = 0; rr < 4; rr++) {
            int rl = warp * 4 + rr;
            int row = r0 + rl;
            float acc = 0.f;
            if (row < n) {
                int beg = g_rowptr[row], end = g_rowptr[row + 1];
                for (int j = beg + lane; j < end; j += 32)
                    acc += x[g_csrc[j]];
            }
            #pragma unroll
            for (int o = 16; o > 0; o >>= 1)
                acc += __shfl_xor_sync(0xFFFFFFFFu, acc, o);
            if (lane == 0)
                sm.l0.xr[rl] = (row < n) ? (acc + x[row]) : 0.f;
        }
        __syncthreads();
        int c = t & 63, g4 = t >> 6;   // g4 in 0..7, 8 rows each
        float wc = w1_0[c], bc = b1[c];
        float s = 0.f, q = 0.f;
        #pragma unroll
        for (int i = 0; i < 8; i++) {
            int row = r0 + g4 * 8 + i;
            if (row < n) {
                float zv = sm.l0.xr[g4 * 8 + i] * wc + bc;
                g_z[(size_t)row * HID + c] = zv;
                s += zv; q += zv * zv;
            }
        }
        atomicAdd(&sm.l0.st[c], s);
        atomicAdd(&sm.l0.st[64 + c], q);
        __syncthreads();
    }
    if (t < 128) atomicAdd(&g_statp[slice + t], sm.l0.st[t]);
    gbar();

    // ---------- layers ----------
    for (int l = 0; l < LAY; l++) {
        // ----- gemm1 + unroll-4 fp16 gather (l >= 1) -----
        if (l > 0) {
            int pc = (l - 1) * HID;
            int pso = (l - 1) * 256 + 128;
            if (t < 64) {
                float s1 = 0.f, s2 = 0.f;
                #pragma unroll 4
                for (int sl = 0; sl < NSLICE; sl++) {
                    const float* sp = g_statp + sl * STATSZ + pso;
                    s1 += __ldcg(sp + t);
                    s2 += __ldcg(sp + 64 + t);
                }
                float mean = s1 * invN;
                float var  = s2 * invN - mean * mean;
                float a = go[pc + t] * rsqrtf(var + BN_EPS);
                sm.g.a[t] = a;
                sm.g.b[t] = bo[pc + t] - mean * a;
                sm.g.bias[t] = b1[l * HID + t];
            }
            const float* w = w1_rest + (size_t)(l - 1) * 4096;
            for (int idx = t; idx < 4096; idx += NT)
                sm.g.w[idx >> 6][idx & 63] = w[idx];
            for (int i = t; i < 128; i += NT) sm.g.st[i] = 0.f;
            __syncthreads();

            int half = lane >> 4, c4 = lane & 15;
            float4 ca = *(const float4*)&sm.g.a[c4 * 4];
            float4 cb = *(const float4*)&sm.g.b[c4 * 4];
            int so = l * 256;

            for (int tile = b; tile < ntiles; tile += nb) {
                int r0 = tile * 64;
                for (int rr = 0; rr < 4; rr++) {
                    int rl = warp * 4 + rr;
                    int row = r0 + rl;
                    float4 A = make_float4(0.f, 0.f, 0.f, 0.f);
                    if (row < n) {
                        int beg = g_rowptr[row], end = g_rowptr[row + 1];
                        int j = beg + half;
                        auto accum = [&](uint2 raw) {
                            float2 f01 = __half22float2(*(__half2*)&raw.x);
                            float2 f23 = __half22float2(*(__half2*)&raw.y);
                            A.x += fmaxf(fmaf(f01.x, ca.x, cb.x), 0.f);
                            A.y += fmaxf(fmaf(f01.y, ca.y, cb.y), 0.f);
                            A.z += fmaxf(fmaf(f23.x, ca.z, cb.z), 0.f);
                            A.w += fmaxf(fmaf(f23.y, ca.w, cb.w), 0.f);
                        };
                        while (j + 6 < end) {
                            int s0 = g_csrc[j];
                            int s1 = g_csrc[j + 2];
                            int s2 = g_csrc[j + 4];
                            int s3 = g_csrc[j + 6];
                            uint2 w0 = *(const uint2*)(g_h16 + (size_t)s0 * HL + pc + c4 * 4);
                            uint2 w1 = *(const uint2*)(g_h16 + (size_t)s1 * HL + pc + c4 * 4);
                            uint2 w2v = *(const uint2*)(g_h16 + (size_t)s2 * HL + pc + c4 * 4);
                            uint2 w3 = *(const uint2*)(g_h16 + (size_t)s3 * HL + pc + c4 * 4);
                            accum(w0); accum(w1); accum(w2v); accum(w3);
                            j += 8;
                        }
                        for (; j < end; j += 2) {
                            int sj = g_csrc[j];
                            uint2 wj = *(const uint2*)(g_h16 + (size_t)sj * HL + pc + c4 * 4);
                            accum(wj);
                        }
                    }
                    A.x += __shfl_xor_sync(0xFFFFFFFFu, A.x, 16);
                    A.y += __shfl_xor_sync(0xFFFFFFFFu, A.y, 16);
                    A.z += __shfl_xor_sync(0xFFFFFFFFu, A.z, 16);
                    A.w += __shfl_xor_sync(0xFFFFFFFFu, A.w, 16);
                    if (half == 0) {
                        if (row < n) {
                            uint2 raw = *(const uint2*)(g_h16 + (size_t)row * HL + pc + c4 * 4);
                            float2 f01 = __half22float2(*(__half2*)&raw.x);
                            float2 f23 = __half22float2(*(__half2*)&raw.y);
                            A.x += fmaxf(fmaf(f01.x, ca.x, cb.x), 0.f);
                            A.y += fmaxf(fmaf(f01.y, ca.y, cb.y), 0.f);
                            A.z += fmaxf(fmaf(f23.x, ca.z, cb.z), 0.f);
                            A.w += fmaxf(fmaf(f23.y, ca.w, cb.w), 0.f);
                        }
                        float* ip = &sm.g.in[rl][c4 * 4];
                        ip[0] = A.x; ip[1] = A.y; ip[2] = A.z; ip[3] = A.w;
                    }
                }
                __syncthreads();
                // GEMM: 512 threads, 8 outputs each
                int r = t & 63, c0 = (t >> 6) * 8;
                float acc[8];
                #pragma unroll
                for (int j = 0; j < 8; j++) acc[j] = sm.g.bias[c0 + j];
                #pragma unroll
                for (int k = 0; k < 64; k++) {
                    float a = sm.g.in[r][k];
                    float4 wv0 = *(const float4*)&sm.g.w[k][c0];
                    float4 wv1 = *(const float4*)&sm.g.w[k][c0 + 4];
                    acc[0] = fmaf(a, wv0.x, acc[0]);
                    acc[1] = fmaf(a, wv0.y, acc[1]);
                    acc[2] = fmaf(a, wv0.z, acc[2]);
                    acc[3] = fmaf(a, wv0.w, acc[3]);
                    acc[4] = fmaf(a, wv1.x, acc[4]);
                    acc[5] = fmaf(a, wv1.y, acc[5]);
                    acc[6] = fmaf(a, wv1.z, acc[6]);
                    acc[7] = fmaf(a, wv1.w, acc[7]);
                }
                int gr = r0 + r;
                bool valid = gr < n;
                if (valid) {
                    float4* op = (float4*)&g_z[(size_t)gr * HID + c0];
                    op[0] = make_float4(acc[0], acc[1], acc[2], acc[3]);
                    op[1] = make_float4(acc[4], acc[5], acc[6], acc[7]);
                }
                #pragma unroll
                for (int j = 0; j < 8; j++) {
                    float s = valid ? acc[j] : 0.f;
                    float q = s * s;
                    #pragma unroll
                    for (int o = 16; o > 0; o >>= 1) {
                        s += __shfl_down_sync(0xFFFFFFFFu, s, o);
                        q += __shfl_down_sync(0xFFFFFFFFu, q, o);
                    }
                    if (lane == 0) {
                        atomicAdd(&sm.g.st[c0 + j], s);
                        atomicAdd(&sm.g.st[64 + c0 + j], q);
                    }
                }
                __syncthreads();
            }
            if (t < 128) atomicAdd(&g_statp[slice + so + t], sm.g.st[t]);
            gbar();
        }

        // ----- gemm2 -----
        {
            int zso = l * 256;
            if (t < 64) {
                float s1 = 0.f, s2 = 0.f;
                #pragma unroll 4
                for (int sl = 0; sl < NSLICE; sl++) {
                    const float* sp = g_statp + sl * STATSZ + zso;
                    s1 += __ldcg(sp + t);
                    s2 += __ldcg(sp + 64 + t);
                }
                float mean = s1 * invN;
                float var  = s2 * invN - mean * mean;
                float a = gm[l * HID + t] * rsqrtf(var + BN_EPS);
                sm.g.a[t] = a;
                sm.g.b[t] = bm[l * HID + t] - mean * a;
                sm.g.bias[t] = b2[l * HID + t];
            }
            const float* w = w2 + (size_t)l * 4096;
            for (int idx = t; idx < 4096; idx += NT)
                sm.g.w[idx >> 6][idx & 63] = w[idx];
            for (int i = t; i < 128; i += NT) sm.g.st[i] = 0.f;
            __syncthreads();

            int vso = l * 256 + 128;

            for (int tile = b; tile < ntiles; tile += nb) {
                int r0 = tile * 64;
                for (int idx = t; idx < 1024; idx += NT) {
                    int r = idx >> 4, k4 = idx & 15;
                    int gr = r0 + r;
                    float4 val = make_float4(0.f, 0.f, 0.f, 0.f);
                    if (gr < n) {
                        float4 z = *(const float4*)(g_z + (size_t)gr * HID + k4 * 4);
                        val.x = fmaxf(fmaf(z.x, sm.g.a[k4*4+0], sm.g.b[k4*4+0]), 0.f);
                        val.y = fmaxf(fmaf(z.y, sm.g.a[k4*4+1], sm.g.b[k4*4+1]), 0.f);
                        val.z = fmaxf(fmaf(z.z, sm.g.a[k4*4+2], sm.g.b[k4*4+2]), 0.f);
                        val.w = fmaxf(fmaf(z.w, sm.g.a[k4*4+3], sm.g.b[k4*4+3]), 0.f);
                    }
                    sm.g.in[r][k4*4+0] = val.x;
                    sm.g.in[r][k4*4+1] = val.y;
                    sm.g.in[r][k4*4+2] = val.z;
                    sm.g.in[r][k4*4+3] = val.w;
                }
                __syncthreads();
                int r = t & 63, c0 = (t >> 6) * 8;
                float acc[8];
                #pragma unroll
                for (int j = 0; j < 8; j++) acc[j] = sm.g.bias[c0 + j];
                #pragma unroll
                for (int k = 0; k < 64; k++) {
                    float a = sm.g.in[r][k];
                    float4 wv0 = *(const float4*)&sm.g.w[k][c0];
                    float4 wv1 = *(const float4*)&sm.g.w[k][c0 + 4];
                    acc[0] = fmaf(a, wv0.x, acc[0]);
                    acc[1] = fmaf(a, wv0.y, acc[1]);
                    acc[2] = fmaf(a, wv0.z, acc[2]);
                    acc[3] = fmaf(a, wv0.w, acc[3]);
                    acc[4] = fmaf(a, wv1.x, acc[4]);
                    acc[5] = fmaf(a, wv1.y, acc[5]);
                    acc[6] = fmaf(a, wv1.z, acc[6]);
                    acc[7] = fmaf(a, wv1.w, acc[7]);
                }
                int gr = r0 + r;
                bool valid = gr < n;
                if (valid) {
                    uint4 pk;
                    __half2* ph = (__half2*)&pk;
                    ph[0] = __float22half2_rn(make_float2(acc[0], acc[1]));
                    ph[1] = __float22half2_rn(make_float2(acc[2], acc[3]));
                    ph[2] = __float22half2_rn(make_float2(acc[4], acc[5]));
                    ph[3] = __float22half2_rn(make_float2(acc[6], acc[7]));
                    *(uint4*)(g_h16 + (size_t)gr * HL + l * HID + c0) = pk;
                }
                #pragma unroll
                for (int j = 0; j < 8; j++) {
                    float s = valid ? acc[j] : 0.f;
                    float q = s * s;
                    #pragma unroll
                    for (int o = 16; o > 0; o >>= 1) {
                        s += __shfl_down_sync(0xFFFFFFFFu, s, o);
                        q += __shfl_down_sync(0xFFFFFFFFu, q, o);
                    }
                    if (lane == 0) {
                        atomicAdd(&sm.g.st[c0 + j], s);
                        atomicAdd(&sm.g.st[64 + c0 + j], q);
                    }
                }
                __syncthreads();
            }
            if (t < 128) atomicAdd(&g_statp[slice + vso + t], sm.g.st[t]);
            gbar();
        }
    }

    // ---------- pool + classifier (warp per graph, half2 reads) ----------
    for (int c = t; c < HL; c += NT) {
        int l = c >> 6, ch = c & 63;
        int vso = l * 256 + 128;
        float s1 = 0.f, s2 = 0.f;
        for (int sl = 0; sl < NSLICE; sl++) {
            const float* sp = g_statp + sl * STATSZ + vso;
            s1 += __ldcg(sp + ch);
            s2 += __ldcg(sp + 64 + ch);
        }
        float mean = s1 * invN;
        float var  = s2 * invN - mean * mean;
        float a = go[c] * rsqrtf(var + BN_EPS);
        sm.p.a[c] = a;
        sm.p.b[c] = bo[c] - mean * a;
    }
    __syncthreads();
    {
        int is64 = g_is64_b;
        int warpsTotal = nb * 16;
        int gw = b * 16 + warp;
        for (int g = gw; g < GNUM; g += warpsTotal) {
            int se = n;
            if (lane < 2) {
                int key = g + lane;
                int lo = 0, hi = n;
                while (lo < hi) {
                    int mid = (lo + hi) >> 1;
                    if ((int)ldidx(batch, mid, is64) < key) lo = mid + 1;
                    else hi = mid;
                }
                se = lo;
            }
            int s0 = __shfl_sync(0xFFFFFFFFu, se, 0);
            int e0 = __shfl_sync(0xFFFFFFFFu, se, 1);
            float acc0[5], acc1[5];
            #pragma unroll
            for (int k = 0; k < 5; k++) { acc0[k] = 0.f; acc1[k] = 0.f; }
            float xsum = 0.f;
            int cbase = lane * 2;
            for (int r = s0; r < e0; r++) {
                xsum += x[r];
                const __half2* rp = (const __half2*)(g_h16 + (size_t)r * HL);
                #pragma unroll
                for (int k = 0; k < 5; k++) {
                    float2 f = __half22float2(rp[k * 32 + lane]);
                    int c = k * 64 + cbase;
                    acc0[k] += fmaxf(fmaf(f.x, sm.p.a[c], sm.p.b[c]), 0.f);
                    acc1[k] += fmaxf(fmaf(f.y, sm.p.a[c + 1], sm.p.b[c + 1]), 0.f);
                }
            }
            float o0 = 0.f, o1 = 0.f;
            #pragma unroll
            for (int k = 0; k < 5; k++) {
                int c = k * 64 + cbase;
                o0 = fmaf(acc0[k], lin_w[(1 + c) * 2 + 0], o0);
                o1 = fmaf(acc0[k], lin_w[(1 + c) * 2 + 1], o1);
                o0 = fmaf(acc1[k], lin_w[(2 + c) * 2 + 0], o0);
                o1 = fmaf(acc1[k], lin_w[(2 + c) * 2 + 1], o1);
            }
            #pragma unroll
            for (int o = 16; o > 0; o >>= 1) {
                o0 += __shfl_down_sync(0xFFFFFFFFu, o0, o);
                o1 += __shfl_down_sync(0xFFFFFFFFu, o1, o);
            }
            if (lane == 0) {
                out[g * 2 + 0] = o0 + xsum * lin_w[0] + lin_b[0];
                out[g * 2 + 1] = o1 + xsum * lin_w[1] + lin_b[1];
            }
        }
    }
}

// ---------------- launch ----------------
extern "C" void kernel_launch(void* const* d_in, const int* in_sizes, int n_in,
                              void* d_out, int out_size)
{
    const float* x      = (const float*)d_in[0];
    const void*  ei     = d_in[1];
    const void*  batch  = d_in[2];
    const float* w1_0   = (const float*)d_in[3];
    const float* w1_rest= (const float*)d_in[4];
    const float* b1     = (const float*)d_in[5];
    const float* gm     = (const float*)d_in[6];
    const float* bm     = (const float*)d_in[7];
    const float* w2     = (const float*)d_in[8];
    const float* b2     = (const float*)d_in[9];
    const float* go     = (const float*)d_in[10];
    const float* bo     = (const float*)d_in[11];
    const float* lin_w  = (const float*)d_in[12];
    const float* lin_b  = (const float*)d_in[13];
    float* out = (float*)d_out;

    int N = in_sizes[0];
    int E = in_sizes[1] / 2;
    float invN = 1.f / (float)N;

    fused_all<<<PB, NT>>>(x, ei, batch, w1_0, w1_rest, b1, gm, bm,
                          w2, b2, go, bo, lin_w, lin_b, out,
                          N, E, in_sizes[2], invN);
}